// round 8
// baseline (speedup 1.0000x reference)
#include <cuda_runtime.h>
#include <math.h>

#define LAMDA 0.1f
#define T_AVG 8192
#define THREADS 256
#define T4 (T_AVG / 4)          // 2048 float4
#define RING 8                  // T4 / THREADS: c at iter k == a at iter k+8
#define GRP (RING * THREADS)    // 2048 float4 per unrolled ring group

// Accumulators: zero at module load; reset by the last block each launch,
// so every graph replay starts clean. Counter self-wraps via atomicInc.
__device__ float g_acc0;
__device__ float g_acc1;
__device__ unsigned int g_count;

__device__ __forceinline__ float sq4(float4 a, float4 b) {
    float d0 = a.x - b.x;
    float d1 = a.y - b.y;
    float d2 = a.z - b.z;
    float d3 = a.w - b.w;
    return d0 * d0 + d1 * d1 + d2 * d2 + d3 * d3;
}

__global__ void __launch_bounds__(THREADS, 4) fused_loss_kernel(
    const float4* __restrict__ in,
    const float4* __restrict__ tg,
    float* __restrict__ out,
    int n4, int lim4 /* = n4 - T4 */, int chunk,
    float inv_n, int nSteps)
{
    float s_mse = 0.0f;
    float s_cyc = 0.0f;

    const int base = blockIdx.x * chunk;
    const int end = min(base + chunk, n4);
    const int end_cyc = min(end, lim4);
    int i = base + threadIdx.x;

    // ── Depth-8 register ring. Thread t's c-load (address i+T4) at iteration
    //    k is its a-value at iteration k+8 (since T4 == 8*THREADS). Each
    //    element of `in` is loaded ONCE; 8 iterations of slack hide warm-L2
    //    latency (~260 cyc) behind ~8 groups of issue work + warp overlap.
    if (i + GRP <= end_cyc + threadIdx.x) {  // ring loop runs at least once
        float4 ring[RING];
        #pragma unroll
        for (int j = 0; j < RING; j++) ring[j] = in[i + j * THREADS];

        for (; i - threadIdx.x + GRP <= end_cyc; i += GRP) {
            #pragma unroll
            for (int j = 0; j < RING; j++) {
                int idx = i + j * THREADS;
                float4 a = ring[j];
                float4 c = in[idx + T4];
                float4 b = __ldcs(&tg[idx]);
                ring[j] = c;
                s_mse += sq4(a, b);
                s_cyc += sq4(a, c);
            }
        }
        // Leftover ring values are discarded; tails below reload (L2 hits).
    }

    // Tail of the cyc region (direct loads).
    for (; i < end_cyc; i += THREADS) {
        float4 a = in[i];
        float4 b = __ldcs(&tg[i]);
        float4 c = in[i + T4];
        s_mse += sq4(a, b);
        s_cyc += sq4(a, c);
    }
    // MSE-only region (last T elements of n; only the final data block).
    for (; i < end; i += THREADS) {
        float4 a = in[i];
        float4 b = __ldcs(&tg[i]);
        s_mse += sq4(a, b);
    }

    // Warp reduction
    #pragma unroll
    for (int off = 16; off > 0; off >>= 1) {
        s_mse += __shfl_xor_sync(0xffffffffu, s_mse, off);
        s_cyc += __shfl_xor_sync(0xffffffffu, s_cyc, off);
    }

    __shared__ float sm_mse[THREADS / 32];
    __shared__ float sm_cyc[THREADS / 32];
    int wid = threadIdx.x >> 5;
    int lid = threadIdx.x & 31;
    if (lid == 0) {
        sm_mse[wid] = s_mse;
        sm_cyc[wid] = s_cyc;
    }
    __syncthreads();

    if (threadIdx.x == 0) {
        float bm = sm_mse[0];
        float bc = sm_cyc[0];
        #pragma unroll
        for (int w = 1; w < THREADS / 32; w++) {
            bm += sm_mse[w];
            bc += sm_cyc[w];
        }
        atomicAdd(&g_acc0, bm);
        atomicAdd(&g_acc1, bc);
        __threadfence();
        // atomicInc wraps to 0 when old == gridDim.x-1 -> self-resetting counter
        unsigned int ticket = atomicInc(&g_count, gridDim.x - 1);
        if (ticket == gridDim.x - 1) {
            float tot_mse = atomicAdd(&g_acc0, 0.0f);
            float tot_cyc = atomicAdd(&g_acc1, 0.0f);
            float l1 = (nSteps != 1) ? (LAMDA * sqrtf(tot_cyc)) : 0.0f;
            out[0] = tot_mse * inv_n + l1;
            // Reset for next graph replay.
            g_acc0 = 0.0f;
            g_acc1 = 0.0f;
        }
    }
}

extern "C" void kernel_launch(void* const* d_in, const int* in_sizes, int n_in,
                              void* d_out, int out_size) {
    const float* input  = (const float*)d_in[0];
    const float* target = (const float*)d_in[1];
    float* out = (float*)d_out;

    int n = in_sizes[0];         // 16,777,216
    int n4 = n / 4;
    int T = T_AVG;               // 8192 (fixed for this problem)
    int nSteps = n / T;          // 2048
    int lim4 = n4 - T4;          // (N-1)*T / 4

    // Contiguous per-block chunk, rounded up to a full ring group so full
    // blocks run only the ring path.
    const int blocks = 148 * 4;  // 592 capacity; ~512 do work at this size
    int chunk = (n4 + blocks - 1) / blocks;
    chunk = (chunk + GRP - 1) / GRP * GRP;

    fused_loss_kernel<<<blocks, THREADS>>>(
        (const float4*)input, (const float4*)target, out,
        n4, lim4, chunk, 1.0f / (float)n, nSteps);
}

// round 9
// speedup vs baseline: 1.5183x; 1.5183x over previous
#include <cuda_runtime.h>
#include <math.h>

#define LAMDA 0.1f
#define T_AVG 8192
#define THREADS 256
#define T4 (T_AVG / 4)          // 2048 float4 = cyclic offset
#define RING 8                  // T4 / THREADS
#define GRP (RING * THREADS)    // 2048 float4 = T4: one ring revolution

// Accumulators: zero at module load; reset by the last block each launch,
// so every graph replay starts clean. Counter self-wraps via atomicInc.
__device__ float g_acc0;
__device__ float g_acc1;
__device__ unsigned int g_count;

__device__ __forceinline__ float sq4(float4 a, float4 b) {
    float d0 = a.x - b.x;
    float d1 = a.y - b.y;
    float d2 = a.z - b.z;
    float d3 = a.w - b.w;
    return d0 * d0 + d1 * d1 + d2 * d2 + d3 * d3;
}

__global__ void __launch_bounds__(THREADS, 4) fused_loss_kernel(
    const float4* __restrict__ in,
    const float4* __restrict__ tg,
    float* __restrict__ out,
    int n4, int chunk,
    float inv_n, int nSteps)
{
    // Thread-private SMEM history ring: slot j holds this thread's in-value
    // from 8 iterations (= T4 elements) ago. No cross-thread sharing -> no
    // __syncthreads in the hot loop, no register pressure.
    __shared__ float4 ring[RING * THREADS];

    float s_mse = 0.0f;
    float s_cyc = 0.0f;

    const int base = blockIdx.x * chunk;       // chunk is a multiple of T4
    const int end = min(base + chunk, n4);
    const int tid = threadIdx.x;
    int i = base + tid;

    // ── Prologue: first T4 elements of the chunk. Fills ring slots 0..7.
    //    Cyc pairing is (i - T4, i): partner comes from a direct load
    //    (previous block's territory), except for the global first block.
    {
        const int pro_end = min(base + T4, end);
        int k = 0;
        for (; i < pro_end; i += THREADS, k++) {
            float4 a = in[i];
            float4 b = __ldcs(&tg[i]);
            s_mse += sq4(a, b);
            if (i >= T4) {
                float4 old = in[i - T4];
                s_cyc += sq4(old, a);
            }
            ring[k * THREADS + tid] = a;
        }
    }

    // ── Main: each element of `in` loaded ONCE; its T4-ago partner comes
    //    from the smem ring. 8x unrolled so ring slots are compile-time.
    for (; i - tid + GRP <= end; i += GRP) {
        #pragma unroll
        for (int j = 0; j < RING; j++) {
            int idx = i + j * THREADS;
            float4 a = in[idx];
            float4 b = __ldcs(&tg[idx]);
            float4 old = ring[j * THREADS + tid];
            ring[j * THREADS + tid] = a;
            s_mse += sq4(a, b);
            s_cyc += sq4(old, a);
        }
    }

    // ── General tail (only if chunk wasn't aligned / last partial block):
    //    direct loads for both streams.
    for (; i < end; i += THREADS) {
        float4 a = in[i];
        float4 b = __ldcs(&tg[i]);
        s_mse += sq4(a, b);
        if (i >= T4) {
            float4 old = in[i - T4];
            s_cyc += sq4(old, a);
        }
    }

    // Warp reduction
    #pragma unroll
    for (int off = 16; off > 0; off >>= 1) {
        s_mse += __shfl_xor_sync(0xffffffffu, s_mse, off);
        s_cyc += __shfl_xor_sync(0xffffffffu, s_cyc, off);
    }

    __shared__ float sm_mse[THREADS / 32];
    __shared__ float sm_cyc[THREADS / 32];
    int wid = threadIdx.x >> 5;
    int lid = threadIdx.x & 31;
    if (lid == 0) {
        sm_mse[wid] = s_mse;
        sm_cyc[wid] = s_cyc;
    }
    __syncthreads();

    if (threadIdx.x == 0) {
        float bm = sm_mse[0];
        float bc = sm_cyc[0];
        #pragma unroll
        for (int w = 1; w < THREADS / 32; w++) {
            bm += sm_mse[w];
            bc += sm_cyc[w];
        }
        atomicAdd(&g_acc0, bm);
        atomicAdd(&g_acc1, bc);
        __threadfence();
        // atomicInc wraps to 0 when old == gridDim.x-1 -> self-resetting counter
        unsigned int ticket = atomicInc(&g_count, gridDim.x - 1);
        if (ticket == gridDim.x - 1) {
            float tot_mse = atomicAdd(&g_acc0, 0.0f);
            float tot_cyc = atomicAdd(&g_acc1, 0.0f);
            float l1 = (nSteps != 1) ? (LAMDA * sqrtf(tot_cyc)) : 0.0f;
            out[0] = tot_mse * inv_n + l1;
            // Reset for next graph replay.
            g_acc0 = 0.0f;
            g_acc1 = 0.0f;
        }
    }
}

extern "C" void kernel_launch(void* const* d_in, const int* in_sizes, int n_in,
                              void* d_out, int out_size) {
    const float* input  = (const float*)d_in[0];
    const float* target = (const float*)d_in[1];
    float* out = (float*)d_out;

    int n = in_sizes[0];         // 16,777,216
    int n4 = n / 4;
    int T = T_AVG;               // 8192 (fixed for this problem)
    int nSteps = n / T;          // 2048

    // Contiguous per-block chunk, rounded up to one ring revolution (T4)
    // so full blocks fill the ring exactly in the prologue.
    const int blocks = 148 * 4;  // 592 launched; ~512 active at this size
    int chunk = (n4 + blocks - 1) / blocks;
    chunk = (chunk + GRP - 1) / GRP * GRP;

    fused_loss_kernel<<<blocks, THREADS>>>(
        (const float4*)input, (const float4*)target, out,
        n4, chunk, 1.0f / (float)n, nSteps);
}

// round 10
// speedup vs baseline: 1.7028x; 1.1215x over previous
#include <cuda_runtime.h>
#include <math.h>

#define LAMDA 0.1f
#define T_AVG 8192
#define THREADS 512
#define T4 (T_AVG / 4)              // 2048 float4 per "row"
#define STRIPES (T4 / THREADS)      // 4 column stripes
#define SLABS 74                    // row-pair slabs
#define BLOCKS (STRIPES * SLABS)    // 296 = 2 CTAs/SM, single wave

// Accumulators: zero at module load; reset by the last block each launch,
// so every graph replay starts clean. Counter self-wraps via atomicInc.
__device__ float g_acc0;
__device__ float g_acc1;
__device__ unsigned int g_count;

__device__ __forceinline__ float sq4(float4 a, float4 b) {
    float d0 = a.x - b.x;
    float d1 = a.y - b.y;
    float d2 = a.z - b.z;
    float d3 = a.w - b.w;
    return d0 * d0 + d1 * d1 + d2 * d2 + d3 * d3;
}

// View in/tg as [nRows x T4] float4. Thread owns one column; walks row-pairs.
// Pair p covers rows (2p, 2p+1): mse for both rows, cyc diff (2p,2p+1) direct,
// cyc diff (2p-1,2p) via the carried a1 of the previous pair (or a direct
// boundary load for the slab's first pair). Every in element is loaded ONCE
// (+1 boundary row per slab). tg uses __ldcs so `in` stays L2-resident
// across graph replays.
__global__ void __launch_bounds__(THREADS, 2) fused_loss_kernel(
    const float4* __restrict__ in,
    const float4* __restrict__ tg,
    float* __restrict__ out,
    int nRows, int pairsPerSlab,
    float inv_n, int nSteps)
{
    float s_mse = 0.0f;
    float s_cyc = 0.0f;

    const int stripe = blockIdx.x % STRIPES;
    const int slab = blockIdx.x / STRIPES;
    const int col = stripe * THREADS + threadIdx.x;
    const int totalPairs = nRows >> 1;

    int p0 = slab * pairsPerSlab;
    int p1 = min(p0 + pairsPerSlab, totalPairs);

    if (p0 < p1) {
        const float4* ip = in + col;
        const float4* tp = tg + col;
        int off = 2 * p0 * T4;

        float4 carry;
        // Slab-boundary diff (2p0-1, 2p0): direct load of the previous row.
        if (p0 > 0) {
            carry = ip[off - T4];
        }

        // First pair (peeled: carry diff conditional on p0>0).
        {
            float4 a0 = ip[off];
            float4 a1 = ip[off + T4];
            float4 b0 = __ldcs(&tp[off]);
            float4 b1 = __ldcs(&tp[off + T4]);
            s_mse += sq4(a0, b0);
            s_mse += sq4(a1, b1);
            s_cyc += sq4(a0, a1);
            if (p0 > 0) s_cyc += sq4(carry, a0);
            carry = a1;
            off += 2 * T4;
        }

        // Main pair loop, 2x unrolled (8 front-batched LDG.128s).
        int p = p0 + 1;
        for (; p + 1 < p1; p += 2, off += 4 * T4) {
            float4 a0 = ip[off];
            float4 a1 = ip[off + T4];
            float4 a2 = ip[off + 2 * T4];
            float4 a3 = ip[off + 3 * T4];
            float4 b0 = __ldcs(&tp[off]);
            float4 b1 = __ldcs(&tp[off + T4]);
            float4 b2 = __ldcs(&tp[off + 2 * T4]);
            float4 b3 = __ldcs(&tp[off + 3 * T4]);
            s_mse += sq4(a0, b0);
            s_mse += sq4(a1, b1);
            s_mse += sq4(a2, b2);
            s_mse += sq4(a3, b3);
            s_cyc += sq4(carry, a0);   // (2p-1, 2p)
            s_cyc += sq4(a0, a1);      // (2p, 2p+1)
            s_cyc += sq4(a1, a2);      // (2p+1, 2p+2)
            s_cyc += sq4(a2, a3);      // (2p+2, 2p+3)
            carry = a3;
        }
        // Remaining single pair.
        for (; p < p1; p++, off += 2 * T4) {
            float4 a0 = ip[off];
            float4 a1 = ip[off + T4];
            float4 b0 = __ldcs(&tp[off]);
            float4 b1 = __ldcs(&tp[off + T4]);
            s_mse += sq4(a0, b0);
            s_mse += sq4(a1, b1);
            s_cyc += sq4(carry, a0);
            s_cyc += sq4(a0, a1);
            carry = a1;
        }

        // Generic safety: odd trailing row (not hit for nRows=2048).
        if ((nRows & 1) && p1 == totalPairs) {
            int r = nRows - 1;
            float4 a = ip[r * T4];
            float4 b = __ldcs(&tp[r * T4]);
            s_mse += sq4(a, b);
            s_cyc += sq4(carry, a);   // carry == row nRows-2
        }
    }

    // Warp reduction
    #pragma unroll
    for (int off = 16; off > 0; off >>= 1) {
        s_mse += __shfl_xor_sync(0xffffffffu, s_mse, off);
        s_cyc += __shfl_xor_sync(0xffffffffu, s_cyc, off);
    }

    __shared__ float sm_mse[THREADS / 32];
    __shared__ float sm_cyc[THREADS / 32];
    int wid = threadIdx.x >> 5;
    int lid = threadIdx.x & 31;
    if (lid == 0) {
        sm_mse[wid] = s_mse;
        sm_cyc[wid] = s_cyc;
    }
    __syncthreads();

    if (threadIdx.x == 0) {
        float bm = sm_mse[0];
        float bc = sm_cyc[0];
        #pragma unroll
        for (int w = 1; w < THREADS / 32; w++) {
            bm += sm_mse[w];
            bc += sm_cyc[w];
        }
        atomicAdd(&g_acc0, bm);
        atomicAdd(&g_acc1, bc);
        __threadfence();
        // atomicInc wraps to 0 when old == gridDim.x-1 -> self-resetting counter
        unsigned int ticket = atomicInc(&g_count, gridDim.x - 1);
        if (ticket == gridDim.x - 1) {
            float tot_mse = atomicAdd(&g_acc0, 0.0f);
            float tot_cyc = atomicAdd(&g_acc1, 0.0f);
            float l1 = (nSteps != 1) ? (LAMDA * sqrtf(tot_cyc)) : 0.0f;
            out[0] = tot_mse * inv_n + l1;
            // Reset for next graph replay.
            g_acc0 = 0.0f;
            g_acc1 = 0.0f;
        }
    }
}

extern "C" void kernel_launch(void* const* d_in, const int* in_sizes, int n_in,
                              void* d_out, int out_size) {
    const float* input  = (const float*)d_in[0];
    const float* target = (const float*)d_in[1];
    float* out = (float*)d_out;

    int n = in_sizes[0];         // 16,777,216
    int n4 = n / 4;
    int T = T_AVG;               // 8192 (fixed for this problem)
    int nSteps = n / T;          // 2048
    int nRows = n4 / T4;         // 2048 rows of T4 float4
    int totalPairs = nRows / 2;  // 1024
    int pairsPerSlab = (totalPairs + SLABS - 1) / SLABS;  // 14

    fused_loss_kernel<<<BLOCKS, THREADS>>>(
        (const float4*)input, (const float4*)target, out,
        nRows, pairsPerSlab, 1.0f / (float)n, nSteps);
}